// round 1
// baseline (speedup 1.0000x reference)
#include <cuda_runtime.h>

// ---------------------------------------------------------------------------
// NeuralSpline: 5x (conv3x3 s2 VALID + bias -> relu -> BN) -> FC(1568->20,relu)
// -> FC(20->10) -> natural cubic spline coefficients -> piecewise cubic eval
// over every input pixel.
// ---------------------------------------------------------------------------

#define EPSF 1e-5f

// Scratch (device globals; no allocations allowed)
static __device__ float g_buf1[64 * 32 * 127 * 127]; // conv1 out (132 MB)
static __device__ float g_buf2[64 * 32 * 63 * 63];
static __device__ float g_buf3[64 * 32 * 31 * 31];
static __device__ float g_buf4[64 * 32 * 15 * 15];
static __device__ float g_buf5[64 * 32 * 7 * 7];
static __device__ float g_wt1[27 * 32];      // conv1 weights transposed [ic*9+k][oc]
static __device__ float g_wtl[4 * 288 * 32]; // conv2..5 weights transposed [(ic*9+k)][oc]
static __device__ float g_bns[5 * 32];       // BN scale  = g * rsqrt(v+eps)
static __device__ float g_bsh[5 * 32];       // BN shift  = b - m*scale
static __device__ float g_coef[64 * 27];     // per-batch spline coeffs a[9],b[9],c[9]

// ---- packed f32x2 helpers (Blackwell FFMA2; only reachable via PTX) --------
__device__ __forceinline__ unsigned long long pk2(float x) {
    unsigned long long r;
    unsigned u = __float_as_uint(x);
    asm("mov.b64 %0, {%1, %1};" : "=l"(r) : "r"(u));
    return r;
}
__device__ __forceinline__ void ffma2(unsigned long long& a, unsigned long long x,
                                      unsigned long long w) {
    asm("fma.rn.f32x2 %0, %1, %2, %0;" : "+l"(a) : "l"(x), "l"(w));
}
__device__ __forceinline__ float lo32(unsigned long long v) {
    return __uint_as_float((unsigned)(v & 0xffffffffULL));
}
__device__ __forceinline__ float hi32(unsigned long long v) {
    return __uint_as_float((unsigned)(v >> 32));
}

// ---------------------------------------------------------------------------
// prep: BN fold + weight transpose to oc-contiguous layout
// ---------------------------------------------------------------------------
__global__ void prep_kernel(const float* __restrict__ c1w, const float* __restrict__ cw,
                            const float* __restrict__ bng, const float* __restrict__ bnb,
                            const float* __restrict__ bnm, const float* __restrict__ bnv) {
    const int stride = gridDim.x * blockDim.x;
    const int t0 = blockIdx.x * blockDim.x + threadIdx.x;
    for (int i = t0; i < 5 * 32; i += stride) {
        float inv = bng[i] * rsqrtf(bnv[i] + EPSF);
        g_bns[i] = inv;
        g_bsh[i] = bnb[i] - bnm[i] * inv;
    }
    for (int i = t0; i < 27 * 32; i += stride) {
        int oc = i / 27, r = i % 27; // src [oc][ic][kh][kw]
        g_wt1[r * 32 + oc] = c1w[i];
    }
    for (int i = t0; i < 4 * 32 * 288; i += stride) {
        int l = i / 9216, rem = i % 9216;
        int oc = rem / 288, r = rem % 288; // r = ic*9 + kh*3 + kw
        g_wtl[l * 9216 + r * 32 + oc] = cw[i];
    }
}

// ---------------------------------------------------------------------------
// conv1: 3 -> 32 channels, in 255x255, out 127x127.  Tile 16x16 outputs/block,
// each thread computes all 32 oc for one output position (16 packed FFMA2/tap).
// ---------------------------------------------------------------------------
__global__ void __launch_bounds__(256) conv1_kernel(const float* __restrict__ in,
                                                    const float* __restrict__ bias) {
    __shared__ __align__(16) float s_in[3 * 33 * 33];
    __shared__ __align__(16) float s_w[27 * 32];
    const int b = blockIdx.y;
    const int ty0 = (blockIdx.x >> 3) * 16;
    const int tx0 = (blockIdx.x & 7) * 16;

    for (int i = threadIdx.x; i < 27 * 32; i += 256) s_w[i] = g_wt1[i];

    const int iy0 = 2 * ty0, ix0 = 2 * tx0;
    const float* inb = in + (size_t)b * 3 * 255 * 255;
    for (int i = threadIdx.x; i < 3 * 33 * 33; i += 256) {
        int ic = i / 1089, r = i % 1089;
        int y = r / 33, x = r % 33;
        int gy = iy0 + y, gx = ix0 + x;
        s_in[i] = (gy < 255 && gx < 255) ? inb[(ic * 255 + gy) * 255 + gx] : 0.f;
    }
    __syncthreads();

    const int ox = threadIdx.x & 15, oy = threadIdx.x >> 4;
    unsigned long long acc[16];
#pragma unroll
    for (int j = 0; j < 16; j++) acc[j] = 0ULL;

    const float* pin0 = s_in + (2 * oy) * 33 + 2 * ox;
#pragma unroll
    for (int ic = 0; ic < 3; ic++) {
        const float* pin = pin0 + ic * 1089;
        const float* pw0 = s_w + ic * 9 * 32;
#pragma unroll
        for (int kh = 0; kh < 3; kh++) {
#pragma unroll
            for (int kw = 0; kw < 3; kw++) {
                unsigned long long xp = pk2(pin[kh * 33 + kw]);
                const ulonglong2* w2 =
                    reinterpret_cast<const ulonglong2*>(pw0 + (kh * 3 + kw) * 32);
#pragma unroll
                for (int q = 0; q < 8; q++) {
                    ulonglong2 wv = w2[q];
                    ffma2(acc[2 * q + 0], xp, wv.x);
                    ffma2(acc[2 * q + 1], xp, wv.y);
                }
            }
        }
    }

    const int oyg = ty0 + oy, oxg = tx0 + ox;
    if (oyg < 127 && oxg < 127) {
        float* op = g_buf1 + (size_t)b * 32 * 16129 + oyg * 127 + oxg;
#pragma unroll
        for (int j = 0; j < 16; j++) {
            int oc = 2 * j;
            float v0 = fmaxf(lo32(acc[j]) + bias[oc], 0.f) * g_bns[oc] + g_bsh[oc];
            float v1 = fmaxf(hi32(acc[j]) + bias[oc + 1], 0.f) * g_bns[oc + 1] + g_bsh[oc + 1];
            op[(size_t)oc * 16129] = v0;
            op[(size_t)(oc + 1) * 16129] = v1;
        }
    }
}

// ---------------------------------------------------------------------------
// conv2..5: 32 -> 32 channels.  Tile 8x8 outputs x 32 oc per block.
// 256 thr = 64 spatial x 4 groups of 8 oc.  Input staged 16 channels/phase
// to stay under 48 KB static smem (no cudaFuncSetAttribute needed in capture).
// ---------------------------------------------------------------------------
template <int L, int IH, int OH>
__global__ void __launch_bounds__(256) conv32_kernel(const float* __restrict__ bias) {
    constexpr int IW = IH, OW = OH;
    constexpr int TW = (OW + 7) / 8;
    const float* in = (L == 0) ? g_buf1 : (L == 1) ? g_buf2 : (L == 2) ? g_buf3 : g_buf4;
    float* out = (L == 0) ? g_buf2 : (L == 1) ? g_buf3 : (L == 2) ? g_buf4 : g_buf5;

    __shared__ __align__(16) float s_in[16 * 289]; // 16 ch x 17 x 17
    __shared__ __align__(16) float s_w[16 * 288];  // 16 ch x 9 taps x 32 oc

    const int b = blockIdx.y;
    const int ty0 = (blockIdx.x / TW) * 8;
    const int tx0 = (blockIdx.x % TW) * 8;
    const int iy0 = 2 * ty0, ix0 = 2 * tx0;
    const float* inb = in + (size_t)b * 32 * IH * IW;
    const float* wt = g_wtl + L * 9216;

    const int sp = threadIdx.x & 63;
    const int g = threadIdx.x >> 6;
    const int ox = sp & 7, oy = sp >> 3;

    unsigned long long acc[4] = {0ULL, 0ULL, 0ULL, 0ULL};

#pragma unroll
    for (int ph = 0; ph < 2; ph++) {
        if (ph) __syncthreads();
        for (int i = threadIdx.x; i < 16 * 288; i += 256) s_w[i] = wt[ph * 4608 + i];
        for (int i = threadIdx.x; i < 16 * 289; i += 256) {
            int ic = i / 289, r = i % 289;
            int y = r / 17, x = r % 17;
            int gy = iy0 + y, gx = ix0 + x;
            s_in[i] = (gy < IH && gx < IW)
                          ? inb[((size_t)(ph * 16 + ic) * IH + gy) * IW + gx]
                          : 0.f;
        }
        __syncthreads();

        const float* pin0 = s_in + (2 * oy) * 17 + 2 * ox;
        const float* pw0 = s_w + g * 8;
#pragma unroll 2
        for (int ic = 0; ic < 16; ic++) {
            const float* pin = pin0 + ic * 289;
            const float* pw = pw0 + ic * 288;
#pragma unroll
            for (int kh = 0; kh < 3; kh++) {
#pragma unroll
                for (int kw = 0; kw < 3; kw++) {
                    unsigned long long xp = pk2(pin[kh * 17 + kw]);
                    const ulonglong2* w2 =
                        reinterpret_cast<const ulonglong2*>(pw + (kh * 3 + kw) * 32);
                    ulonglong2 wa = w2[0];
                    ulonglong2 wb = w2[1];
                    ffma2(acc[0], xp, wa.x);
                    ffma2(acc[1], xp, wa.y);
                    ffma2(acc[2], xp, wb.x);
                    ffma2(acc[3], xp, wb.y);
                }
            }
        }
    }

    const int oyg = ty0 + oy, oxg = tx0 + ox;
    if (oyg < OH && oxg < OW) {
        const float* bns = g_bns + (L + 1) * 32;
        const float* bsh = g_bsh + (L + 1) * 32;
        float* op = out + ((size_t)b * 32 + g * 8) * OH * OW + oyg * OW + oxg;
#pragma unroll
        for (int j = 0; j < 4; j++) {
            int oc = g * 8 + 2 * j;
            float v0 = fmaxf(lo32(acc[j]) + bias[oc], 0.f) * bns[oc] + bsh[oc];
            float v1 = fmaxf(hi32(acc[j]) + bias[oc + 1], 0.f) * bns[oc + 1] + bsh[oc + 1];
            op[(size_t)(2 * j) * OH * OW] = v0;
            op[(size_t)(2 * j + 1) * OH * OW] = v1;
        }
    }
}

// ---------------------------------------------------------------------------
// FC(1568->20 relu) -> FC(20->10) -> natural-spline second-derivative solve
// (Thomas tridiagonal, fp64) -> per-interval cubic coefficients a,b,c.
// One block per batch element.
// ---------------------------------------------------------------------------
__global__ void __launch_bounds__(256) fc_kernel(const float* __restrict__ l1w,
                                                 const float* __restrict__ l1b,
                                                 const float* __restrict__ l2w,
                                                 const float* __restrict__ l2b) {
    __shared__ float s_y[1568];
    __shared__ float s_h1[20];
    __shared__ float s_ys[10];
    const int b = blockIdx.x;
    const float* yb = g_buf5 + (size_t)b * 1568;
    for (int i = threadIdx.x; i < 1568; i += 256) s_y[i] = yb[i];
    __syncthreads();

    const int warp = threadIdx.x >> 5, lane = threadIdx.x & 31;
    for (int j = warp; j < 20; j += 8) {
        float s = 0.f;
        const float* w = l1w + (size_t)j * 1568;
        for (int k = lane; k < 1568; k += 32) s += s_y[k] * w[k];
#pragma unroll
        for (int o = 16; o > 0; o >>= 1) s += __shfl_down_sync(0xffffffffu, s, o);
        if (lane == 0) s_h1[j] = fmaxf(s + l1b[j], 0.f);
    }
    __syncthreads();

    if (threadIdx.x < 10) {
        float s = l2b[threadIdx.x];
        const float* w = l2w + threadIdx.x * 20;
#pragma unroll
        for (int j = 0; j < 20; j++) s += s_h1[j] * w[j];
        s_ys[threadIdx.x] = s;
    }
    __syncthreads();

    if (threadIdx.x == 0) {
        const double h = 1.0 / 9.0;
        double ys[10];
#pragma unroll
        for (int i = 0; i < 10; i++) ys[i] = (double)s_ys[i];
        // RHS: 6/h^2 * second differences; solve tridiag (1,4,1), M[0]=M[9]=0
        double d[8], cp[8];
        for (int i = 0; i < 8; i++)
            d[i] = (6.0 / (h * h)) * (ys[i + 2] - 2.0 * ys[i + 1] + ys[i]);
        cp[0] = 0.25;
        d[0] *= 0.25;
        for (int i = 1; i < 8; i++) {
            double m = 4.0 - cp[i - 1];
            cp[i] = 1.0 / m;
            d[i] = (d[i] - d[i - 1]) / m;
        }
        double M[10];
        M[0] = 0.0;
        M[9] = 0.0;
        M[8] = d[7];
        for (int i = 6; i >= 0; i--) M[i + 1] = d[i] - cp[i] * M[i + 2];
        float* cf = g_coef + b * 27;
        for (int i = 0; i < 9; i++) {
            cf[i] = (float)((M[i + 1] - M[i]) / (6.0 * h));
            cf[9 + i] = (float)(M[i] * 0.5);
            cf[18 + i] = (float)((ys[i + 1] - ys[i]) / h - (M[i + 1] + 2.0 * M[i]) * (h / 6.0));
        }
    }
}

// ---------------------------------------------------------------------------
// eval: out = ((a*xf + b)*xf + c)*xf with bucket xi = floor(clip(x/h, 0, 8)).
// __fdiv_rn keeps the bucket selection bit-identical to the reference even
// under --use_fast_math (adjacent buckets do NOT agree at knots because the
// reference drops the constant term).
// ---------------------------------------------------------------------------
__global__ void __launch_bounds__(256) eval_kernel(const float* __restrict__ in,
                                                   float* __restrict__ out) {
    __shared__ float s_c[27];
    const int b = blockIdx.y;
    if (threadIdx.x < 27) s_c[threadIdx.x] = g_coef[b * 27 + threadIdx.x];
    __syncthreads();
    const int N = 3 * 255 * 255;
    const float* ib = in + (size_t)b * N;
    float* ob = out + (size_t)b * N;
    const float h = 1.0f / 9.0f;
    for (int i = blockIdx.x * blockDim.x + threadIdx.x; i < N; i += gridDim.x * blockDim.x) {
        float x = ib[i];
        float t = fminf(fmaxf(__fdiv_rn(x, h), 0.f), 8.f);
        int xi = (int)t;
        float xf = x - (float)xi * h;
        float va = s_c[xi], vb = s_c[9 + xi], vc = s_c[18 + xi];
        ob[i] = ((va * xf + vb) * xf + vc) * xf;
    }
}

// ---------------------------------------------------------------------------
extern "C" void kernel_launch(void* const* d_in, const int* in_sizes, int n_in,
                              void* d_out, int out_size) {
    const float* batch = (const float*)d_in[0];
    const float* c1w = (const float*)d_in[1];
    const float* c1b = (const float*)d_in[2];
    const float* cw = (const float*)d_in[3];
    const float* cb = (const float*)d_in[4];
    const float* bng = (const float*)d_in[5];
    const float* bnb = (const float*)d_in[6];
    const float* bnm = (const float*)d_in[7];
    const float* bnv = (const float*)d_in[8];
    const float* l1w = (const float*)d_in[9];
    const float* l1b = (const float*)d_in[10];
    const float* l2w = (const float*)d_in[11];
    const float* l2b = (const float*)d_in[12];
    float* out = (float*)d_out;

    prep_kernel<<<64, 256>>>(c1w, cw, bng, bnb, bnm, bnv);
    conv1_kernel<<<dim3(64, 64), 256>>>(batch, c1b);
    conv32_kernel<0, 127, 63><<<dim3(64, 64), 256>>>(cb + 0);
    conv32_kernel<1, 63, 31><<<dim3(16, 64), 256>>>(cb + 32);
    conv32_kernel<2, 31, 15><<<dim3(4, 64), 256>>>(cb + 64);
    conv32_kernel<3, 15, 7><<<dim3(1, 64), 256>>>(cb + 96);
    fc_kernel<<<64, 256>>>(l1w, l1b, l2w, l2b);
    eval_kernel<<<dim3(128, 64), 256>>>(batch, out);
}

// round 2
// speedup vs baseline: 1.3419x; 1.3419x over previous
#include <cuda_runtime.h>

// ---------------------------------------------------------------------------
// NeuralSpline: 5x (conv3x3 s2 VALID + bias -> relu -> BN) -> FC(1568->20,relu)
// -> FC(20->10) -> natural cubic spline coefficients -> piecewise cubic eval.
//
// R2: register-tiled convs (T=4 spatial x C=8 oc per thread), even/odd
// de-interleaved smem input (conflict-free LDS.128), padded buffer strides
// for aligned STG.128, FFMA2 throughout.
// ---------------------------------------------------------------------------

#define EPSF 1e-5f

// Padded scratch buffers: plane stride = H * align4(W)
static __device__ float g_buf1[64 * 32 * 127 * 128]; // conv1 out
static __device__ float g_buf2[64 * 32 * 63 * 64];
static __device__ float g_buf3[64 * 32 * 31 * 32];
static __device__ float g_buf4[64 * 32 * 15 * 16];
static __device__ float g_buf5[64 * 32 * 7 * 8];
static __device__ float g_wt1[27 * 32];      // conv1 weights [ic*9+tap][oc]
static __device__ float g_wtl[4 * 288 * 32]; // conv2..5 weights [(ic*9+tap)][oc]
static __device__ float g_bns[5 * 32];
static __device__ float g_bsh[5 * 32];
static __device__ float g_coef[64 * 27];

// ---- packed f32x2 helpers ---------------------------------------------------
__device__ __forceinline__ unsigned long long pk2(float x) {
    unsigned long long r;
    unsigned u = __float_as_uint(x);
    asm("mov.b64 %0, {%1, %1};" : "=l"(r) : "r"(u));
    return r;
}
__device__ __forceinline__ void ffma2(unsigned long long& a, unsigned long long x,
                                      unsigned long long w) {
    asm("fma.rn.f32x2 %0, %1, %2, %0;" : "+l"(a) : "l"(x), "l"(w));
}
__device__ __forceinline__ float lo32(unsigned long long v) {
    return __uint_as_float((unsigned)(v & 0xffffffffULL));
}
__device__ __forceinline__ float hi32(unsigned long long v) {
    return __uint_as_float((unsigned)(v >> 32));
}

// ---------------------------------------------------------------------------
__global__ void prep_kernel(const float* __restrict__ c1w, const float* __restrict__ cw,
                            const float* __restrict__ bng, const float* __restrict__ bnb,
                            const float* __restrict__ bnm, const float* __restrict__ bnv) {
    const int stride = gridDim.x * blockDim.x;
    const int t0 = blockIdx.x * blockDim.x + threadIdx.x;
    for (int i = t0; i < 5 * 32; i += stride) {
        float inv = bng[i] * rsqrtf(bnv[i] + EPSF);
        g_bns[i] = inv;
        g_bsh[i] = bnb[i] - bnm[i] * inv;
    }
    for (int i = t0; i < 27 * 32; i += stride) {
        int oc = i / 27, r = i % 27;
        g_wt1[r * 32 + oc] = c1w[i];
    }
    for (int i = t0; i < 4 * 32 * 288; i += stride) {
        int l = i / 9216, rem = i % 9216;
        int oc = rem / 288, r = rem % 288;
        g_wtl[l * 9216 + r * 32 + oc] = cw[i];
    }
}

// ---------------------------------------------------------------------------
// Shared inner compute: given even[0..3], e4, odd[0..3] inputs for one (ic,kh)
// row and a pointer to the 3 taps' weights (8 oc), do 48 FFMA2 into acc[16].
// acc layout: acc[t*4 + q], q = oc-pair index (oc = 2q, 2q+1 within group).
// ---------------------------------------------------------------------------
__device__ __forceinline__ void conv_row_taps(unsigned long long (&acc)[16],
                                              const float4 ev, const float e4,
                                              const float4 od,
                                              const float* __restrict__ pw) {
#pragma unroll
    for (int kw = 0; kw < 3; kw++) {
        float xs0, xs1, xs2, xs3;
        if (kw == 0) { xs0 = ev.x; xs1 = ev.y; xs2 = ev.z; xs3 = ev.w; }
        else if (kw == 1) { xs0 = od.x; xs1 = od.y; xs2 = od.z; xs3 = od.w; }
        else { xs0 = ev.y; xs1 = ev.z; xs2 = ev.w; xs3 = e4; }
        const ulonglong2* w2 = reinterpret_cast<const ulonglong2*>(pw + kw * 32);
        ulonglong2 wa = w2[0];
        ulonglong2 wb = w2[1];
        unsigned long long x0 = pk2(xs0), x1 = pk2(xs1), x2 = pk2(xs2), x3 = pk2(xs3);
        ffma2(acc[0], x0, wa.x);  ffma2(acc[1], x0, wa.y);
        ffma2(acc[2], x0, wb.x);  ffma2(acc[3], x0, wb.y);
        ffma2(acc[4], x1, wa.x);  ffma2(acc[5], x1, wa.y);
        ffma2(acc[6], x1, wb.x);  ffma2(acc[7], x1, wb.y);
        ffma2(acc[8], x2, wa.x);  ffma2(acc[9], x2, wa.y);
        ffma2(acc[10], x2, wb.x); ffma2(acc[11], x2, wb.y);
        ffma2(acc[12], x3, wa.x); ffma2(acc[13], x3, wa.y);
        ffma2(acc[14], x3, wb.x); ffma2(acc[15], x3, wb.y);
    }
}

// Epilogue: bias+relu+BN, transpose acc to per-oc float4, aligned STG.128.
template <int PLANE>
__device__ __forceinline__ void conv_store(const unsigned long long (&acc)[16],
                                           float* __restrict__ op,
                                           const float* __restrict__ bias,
                                           const float* __restrict__ bns,
                                           const float* __restrict__ bsh, int ocbase) {
#pragma unroll
    for (int j = 0; j < 4; j++) {
        int oc0 = ocbase + 2 * j;
        float bi0 = bias[oc0], sc0 = bns[oc0], sh0 = bsh[oc0];
        float bi1 = bias[oc0 + 1], sc1 = bns[oc0 + 1], sh1 = bsh[oc0 + 1];
        float4 v0, v1;
        v0.x = fmaxf(lo32(acc[0 + j]) + bi0, 0.f) * sc0 + sh0;
        v0.y = fmaxf(lo32(acc[4 + j]) + bi0, 0.f) * sc0 + sh0;
        v0.z = fmaxf(lo32(acc[8 + j]) + bi0, 0.f) * sc0 + sh0;
        v0.w = fmaxf(lo32(acc[12 + j]) + bi0, 0.f) * sc0 + sh0;
        v1.x = fmaxf(hi32(acc[0 + j]) + bi1, 0.f) * sc1 + sh1;
        v1.y = fmaxf(hi32(acc[4 + j]) + bi1, 0.f) * sc1 + sh1;
        v1.z = fmaxf(hi32(acc[8 + j]) + bi1, 0.f) * sc1 + sh1;
        v1.w = fmaxf(hi32(acc[12 + j]) + bi1, 0.f) * sc1 + sh1;
        *reinterpret_cast<float4*>(op + (size_t)(2 * j) * PLANE) = v0;
        *reinterpret_cast<float4*>(op + (size_t)(2 * j + 1) * PLANE) = v1;
    }
}

// ---------------------------------------------------------------------------
// conv1: 3 -> 32 ch, 255x255 -> 127x127 (padded stride 128).
// 256 thr: xg(4) x y(16) x g(4 oc-groups of 8).  Tile 16x16 outputs.
// ---------------------------------------------------------------------------
__global__ void __launch_bounds__(256) conv1_kernel(const float* __restrict__ in,
                                                    const float* __restrict__ bias) {
    __shared__ __align__(16) float s_in[3 * 33 * 40]; // even[0..16] | pad | odd[20..35]
    __shared__ __align__(16) float s_w[27 * 32];
    const int b = blockIdx.y;
    const int tx = blockIdx.x & 7, ty = blockIdx.x >> 3;
    const int ox0t = tx * 16, oy0 = ty * 16;
    const int ix0 = 2 * ox0t, iy0 = 2 * oy0;

    for (int i = threadIdx.x; i < 27 * 32; i += 256) s_w[i] = g_wt1[i];
    const float* inb = in + (size_t)b * 3 * 255 * 255;
    for (int i = threadIdx.x; i < 3 * 33 * 33; i += 256) {
        int ic = i / 1089, r = i % 1089;
        int yy = r / 33, xx = r % 33;
        int gy = iy0 + yy, gx = ix0 + xx;
        float v = (gy < 255 && gx < 255) ? inb[(ic * 255 + gy) * 255 + gx] : 0.f;
        s_in[ic * 1320 + yy * 40 + ((xx & 1) ? 20 + (xx >> 1) : (xx >> 1))] = v;
    }
    __syncthreads();

    const int xg = threadIdx.x & 3;
    const int y = (threadIdx.x >> 2) & 15;
    const int g = threadIdx.x >> 6;
    unsigned long long acc[16];
#pragma unroll
    for (int i = 0; i < 16; i++) acc[i] = 0ULL;

    const float* pw0 = s_w + g * 8;
#pragma unroll
    for (int ic = 0; ic < 3; ic++) {
        const float* prb = s_in + ic * 1320 + (2 * y) * 40 + 4 * xg;
#pragma unroll
        for (int kh = 0; kh < 3; kh++) {
            const float* pr = prb + kh * 40;
            float4 ev = *reinterpret_cast<const float4*>(pr);
            float e4 = pr[4];
            float4 od = *reinterpret_cast<const float4*>(pr + 20);
            conv_row_taps(acc, ev, e4, od, pw0 + (ic * 9 + kh * 3) * 32);
        }
    }

    const int oy = oy0 + y;
    const int ox0 = ox0t + 4 * xg; // <= 124 < 128 (padded row)
    if (oy < 127) {
        float* op = g_buf1 + ((size_t)b * 32 + g * 8) * (127 * 128) + (size_t)oy * 128 + ox0;
        conv_store<127 * 128>(acc, op, bias, g_bns, g_bsh, g * 8);
    }
}

// ---------------------------------------------------------------------------
// conv2..5: 32 -> 32 ch.  Tile 16x8 outputs, 128 thr: xg(4) x y(8) x g(4).
// ic phased 8 at a time.  IWS/OWS = padded row strides.
// ---------------------------------------------------------------------------
template <int L, int IH, int IWS, int OH, int OWS>
__global__ void __launch_bounds__(128) conv32_kernel(const float* __restrict__ bias) {
    constexpr int IW = IH, OW = OH;
    constexpr int TX = (OW + 15) / 16;
    const float* in = (L == 0) ? g_buf1 : (L == 1) ? g_buf2 : (L == 2) ? g_buf3 : g_buf4;
    float* out = (L == 0) ? g_buf2 : (L == 1) ? g_buf3 : (L == 2) ? g_buf4 : g_buf5;

    __shared__ __align__(16) float s_in[8 * 17 * 40]; // 8 ic x 17 rows x (even|odd)
    __shared__ __align__(16) float s_w[8 * 288];

    const int b = blockIdx.y;
    const int tx = blockIdx.x % TX, ty = blockIdx.x / TX;
    const int ox0t = tx * 16, oy0 = ty * 8;
    const int ix0 = 2 * ox0t, iy0 = 2 * oy0;
    const float* inb = in + (size_t)b * 32 * IH * IWS;
    const float* wt = g_wtl + L * 9216;

    const int xg = threadIdx.x & 3;
    const int y = (threadIdx.x >> 2) & 7;
    const int g = threadIdx.x >> 5;
    unsigned long long acc[16];
#pragma unroll
    for (int i = 0; i < 16; i++) acc[i] = 0ULL;

    for (int ph = 0; ph < 4; ph++) {
        if (ph) __syncthreads();
        for (int i = threadIdx.x; i < 8 * 288; i += 128) s_w[i] = wt[ph * 2304 + i];
        for (int i = threadIdx.x; i < 8 * 17 * 33; i += 128) {
            int ic = i / 561, r = i % 561;
            int yy = r / 33, xx = r % 33;
            int gy = iy0 + yy, gx = ix0 + xx;
            float v = (gy < IH && gx < IW)
                          ? inb[((size_t)(ph * 8 + ic) * IH + gy) * IWS + gx]
                          : 0.f;
            s_in[ic * 680 + yy * 40 + ((xx & 1) ? 20 + (xx >> 1) : (xx >> 1))] = v;
        }
        __syncthreads();

        const float* pw0 = s_w + g * 8;
#pragma unroll
        for (int ic = 0; ic < 8; ic++) {
            const float* prb = s_in + ic * 680 + (2 * y) * 40 + 4 * xg;
            const float* pw1 = pw0 + ic * 288;
#pragma unroll
            for (int kh = 0; kh < 3; kh++) {
                const float* pr = prb + kh * 40;
                float4 ev = *reinterpret_cast<const float4*>(pr);
                float e4 = pr[4];
                float4 od = *reinterpret_cast<const float4*>(pr + 20);
                conv_row_taps(acc, ev, e4, od, pw1 + kh * 3 * 32);
            }
        }
    }

    const int oy = oy0 + y;
    const int ox0 = ox0t + 4 * xg;
    if (oy < OH && ox0 < OWS) { // float4 lands within padded row
        const float* bns = g_bns + (L + 1) * 32;
        const float* bsh = g_bsh + (L + 1) * 32;
        float* op = out + ((size_t)b * 32 + g * 8) * (OH * OWS) + (size_t)oy * OWS + ox0;
        conv_store<OH * OWS>(acc, op, bias, bns, bsh, g * 8);
    }
}

// ---------------------------------------------------------------------------
// FC(1568->20 relu) -> FC(20->10) -> Thomas tridiagonal spline solve (fp64)
// -> cubic coefficients a,b,c.  One block per batch.  Reads padded buf5.
// ---------------------------------------------------------------------------
__global__ void __launch_bounds__(256) fc_kernel(const float* __restrict__ l1w,
                                                 const float* __restrict__ l1b,
                                                 const float* __restrict__ l2w,
                                                 const float* __restrict__ l2b) {
    __shared__ float s_y[1568];
    __shared__ float s_h1[20];
    __shared__ float s_ys[10];
    const int b = blockIdx.x;
    const float* yb = g_buf5 + (size_t)b * 32 * 7 * 8;
    for (int i = threadIdx.x; i < 1568; i += 256) {
        int oc = i / 49, r = i % 49;
        s_y[i] = yb[oc * 56 + (r / 7) * 8 + (r % 7)];
    }
    __syncthreads();

    const int warp = threadIdx.x >> 5, lane = threadIdx.x & 31;
    for (int j = warp; j < 20; j += 8) {
        float s = 0.f;
        const float* w = l1w + (size_t)j * 1568;
        for (int k = lane; k < 1568; k += 32) s += s_y[k] * w[k];
#pragma unroll
        for (int o = 16; o > 0; o >>= 1) s += __shfl_down_sync(0xffffffffu, s, o);
        if (lane == 0) s_h1[j] = fmaxf(s + l1b[j], 0.f);
    }
    __syncthreads();

    if (threadIdx.x < 10) {
        float s = l2b[threadIdx.x];
        const float* w = l2w + threadIdx.x * 20;
#pragma unroll
        for (int j = 0; j < 20; j++) s += s_h1[j] * w[j];
        s_ys[threadIdx.x] = s;
    }
    __syncthreads();

    if (threadIdx.x == 0) {
        const double h = 1.0 / 9.0;
        double ys[10];
#pragma unroll
        for (int i = 0; i < 10; i++) ys[i] = (double)s_ys[i];
        double d[8], cp[8];
        for (int i = 0; i < 8; i++)
            d[i] = (6.0 / (h * h)) * (ys[i + 2] - 2.0 * ys[i + 1] + ys[i]);
        cp[0] = 0.25;
        d[0] *= 0.25;
        for (int i = 1; i < 8; i++) {
            double m = 4.0 - cp[i - 1];
            cp[i] = 1.0 / m;
            d[i] = (d[i] - d[i - 1]) / m;
        }
        double M[10];
        M[0] = 0.0;
        M[9] = 0.0;
        M[8] = d[7];
        for (int i = 6; i >= 0; i--) M[i + 1] = d[i] - cp[i] * M[i + 2];
        float* cf = g_coef + b * 27;
        for (int i = 0; i < 9; i++) {
            cf[i] = (float)((M[i + 1] - M[i]) / (6.0 * h));
            cf[9 + i] = (float)(M[i] * 0.5);
            cf[18 + i] = (float)((ys[i + 1] - ys[i]) / h - (M[i + 1] + 2.0 * M[i]) * (h / 6.0));
        }
    }
}

// ---------------------------------------------------------------------------
// eval: out = ((a*xf + b)*xf + c)*xf ; xi = floor(clip(x/h, 0, 8)) with
// IEEE division (bucket must match reference exactly at knot boundaries).
// ---------------------------------------------------------------------------
__global__ void __launch_bounds__(256) eval_kernel(const float* __restrict__ in,
                                                   float* __restrict__ out) {
    __shared__ float s_c[27];
    const int b = blockIdx.y;
    if (threadIdx.x < 27) s_c[threadIdx.x] = g_coef[b * 27 + threadIdx.x];
    __syncthreads();
    const int N = 3 * 255 * 255;
    const float* ib = in + (size_t)b * N;
    float* ob = out + (size_t)b * N;
    const float h = 1.0f / 9.0f;
    for (int i = blockIdx.x * blockDim.x + threadIdx.x; i < N; i += gridDim.x * blockDim.x) {
        float x = ib[i];
        float t = fminf(fmaxf(__fdiv_rn(x, h), 0.f), 8.f);
        int xi = (int)t;
        float xf = x - (float)xi * h;
        float va = s_c[xi], vb = s_c[9 + xi], vc = s_c[18 + xi];
        ob[i] = ((va * xf + vb) * xf + vc) * xf;
    }
}

// ---------------------------------------------------------------------------
extern "C" void kernel_launch(void* const* d_in, const int* in_sizes, int n_in,
                              void* d_out, int out_size) {
    const float* batch = (const float*)d_in[0];
    const float* c1w = (const float*)d_in[1];
    const float* c1b = (const float*)d_in[2];
    const float* cw = (const float*)d_in[3];
    const float* cb = (const float*)d_in[4];
    const float* bng = (const float*)d_in[5];
    const float* bnb = (const float*)d_in[6];
    const float* bnm = (const float*)d_in[7];
    const float* bnv = (const float*)d_in[8];
    const float* l1w = (const float*)d_in[9];
    const float* l1b = (const float*)d_in[10];
    const float* l2w = (const float*)d_in[11];
    const float* l2b = (const float*)d_in[12];
    float* out = (float*)d_out;

    prep_kernel<<<64, 256>>>(c1w, cw, bng, bnb, bnm, bnv);
    conv1_kernel<<<dim3(64, 64), 256>>>(batch, c1b);
    conv32_kernel<0, 127, 128, 63, 64><<<dim3(32, 64), 128>>>(cb + 0);
    conv32_kernel<1, 63, 64, 31, 32><<<dim3(8, 64), 128>>>(cb + 32);
    conv32_kernel<2, 31, 32, 15, 16><<<dim3(2, 64), 128>>>(cb + 64);
    conv32_kernel<3, 15, 16, 7, 8><<<dim3(1, 64), 128>>>(cb + 96);
    fc_kernel<<<64, 256>>>(l1w, l1b, l2w, l2b);
    eval_kernel<<<dim3(128, 64), 256>>>(batch, out);
}

// round 3
// speedup vs baseline: 2.0145x; 1.5012x over previous
#include <cuda_runtime.h>
#include <cstdint>

// ---------------------------------------------------------------------------
// NeuralSpline R3: pipelined-fill register-tiled convs + div-free eval.
// ---------------------------------------------------------------------------

#define EPSF 1e-5f

// Padded scratch (+64 floats slack: edge tiles read a few floats past the
// last plane; values are garbage but only ever feed padding outputs).
static __device__ float g_buf1[64 * 32 * 127 * 128 + 64];
static __device__ float g_buf2[64 * 32 * 63 * 64 + 64];
static __device__ float g_buf3[64 * 32 * 31 * 32 + 64];
static __device__ float g_buf4[64 * 32 * 15 * 16 + 64];
static __device__ float g_buf5[64 * 32 * 7 * 8 + 64];
static __device__ float g_wt1[27 * 32];
static __device__ float g_wtl[4 * 288 * 32];
static __device__ float g_bns[5 * 32];
static __device__ float g_bsh[5 * 32];
static __device__ float g_coef[64 * 27];

// ---- packed f32x2 helpers ---------------------------------------------------
__device__ __forceinline__ unsigned long long pk2(float x) {
    unsigned long long r;
    unsigned u = __float_as_uint(x);
    asm("mov.b64 %0, {%1, %1};" : "=l"(r) : "r"(u));
    return r;
}
__device__ __forceinline__ void ffma2(unsigned long long& a, unsigned long long x,
                                      unsigned long long w) {
    asm("fma.rn.f32x2 %0, %1, %2, %0;" : "+l"(a) : "l"(x), "l"(w));
}
__device__ __forceinline__ float lo32(unsigned long long v) {
    return __uint_as_float((unsigned)(v & 0xffffffffULL));
}
__device__ __forceinline__ float hi32(unsigned long long v) {
    return __uint_as_float((unsigned)(v >> 32));
}

// ---------------------------------------------------------------------------
__global__ void prep_kernel(const float* __restrict__ c1w, const float* __restrict__ cw,
                            const float* __restrict__ bng, const float* __restrict__ bnb,
                            const float* __restrict__ bnm, const float* __restrict__ bnv) {
    const int stride = gridDim.x * blockDim.x;
    const int t0 = blockIdx.x * blockDim.x + threadIdx.x;
    for (int i = t0; i < 5 * 32; i += stride) {
        float inv = bng[i] * rsqrtf(bnv[i] + EPSF);
        g_bns[i] = inv;
        g_bsh[i] = bnb[i] - bnm[i] * inv;
    }
    for (int i = t0; i < 27 * 32; i += stride) {
        int oc = i / 27, r = i % 27;
        g_wt1[r * 32 + oc] = c1w[i];
    }
    for (int i = t0; i < 4 * 32 * 288; i += stride) {
        int l = i / 9216, rem = i % 9216;
        int oc = rem / 288, r = rem % 288;
        g_wtl[l * 9216 + r * 32 + oc] = cw[i];
    }
}

// 48 FFMA2 for one (ic,kh) row; packs hoisted across the 3 kw taps.
__device__ __forceinline__ void conv_row_taps(unsigned long long (&acc)[16],
                                              const float4 ev, const float e4,
                                              const float4 od,
                                              const float* __restrict__ pw) {
    unsigned long long pe0 = pk2(ev.x), pe1 = pk2(ev.y), pe2 = pk2(ev.z),
                       pe3 = pk2(ev.w), pe4 = pk2(e4);
    unsigned long long po0 = pk2(od.x), po1 = pk2(od.y), po2 = pk2(od.z), po3 = pk2(od.w);
    {
        const ulonglong2* w2 = reinterpret_cast<const ulonglong2*>(pw);
        ulonglong2 wa = w2[0], wb = w2[1];
        ffma2(acc[0], pe0, wa.x);  ffma2(acc[1], pe0, wa.y);
        ffma2(acc[2], pe0, wb.x);  ffma2(acc[3], pe0, wb.y);
        ffma2(acc[4], pe1, wa.x);  ffma2(acc[5], pe1, wa.y);
        ffma2(acc[6], pe1, wb.x);  ffma2(acc[7], pe1, wb.y);
        ffma2(acc[8], pe2, wa.x);  ffma2(acc[9], pe2, wa.y);
        ffma2(acc[10], pe2, wb.x); ffma2(acc[11], pe2, wb.y);
        ffma2(acc[12], pe3, wa.x); ffma2(acc[13], pe3, wa.y);
        ffma2(acc[14], pe3, wb.x); ffma2(acc[15], pe3, wb.y);
    }
    {
        const ulonglong2* w2 = reinterpret_cast<const ulonglong2*>(pw + 32);
        ulonglong2 wa = w2[0], wb = w2[1];
        ffma2(acc[0], po0, wa.x);  ffma2(acc[1], po0, wa.y);
        ffma2(acc[2], po0, wb.x);  ffma2(acc[3], po0, wb.y);
        ffma2(acc[4], po1, wa.x);  ffma2(acc[5], po1, wa.y);
        ffma2(acc[6], po1, wb.x);  ffma2(acc[7], po1, wb.y);
        ffma2(acc[8], po2, wa.x);  ffma2(acc[9], po2, wa.y);
        ffma2(acc[10], po2, wb.x); ffma2(acc[11], po2, wb.y);
        ffma2(acc[12], po3, wa.x); ffma2(acc[13], po3, wa.y);
        ffma2(acc[14], po3, wb.x); ffma2(acc[15], po3, wb.y);
    }
    {
        const ulonglong2* w2 = reinterpret_cast<const ulonglong2*>(pw + 64);
        ulonglong2 wa = w2[0], wb = w2[1];
        ffma2(acc[0], pe1, wa.x);  ffma2(acc[1], pe1, wa.y);
        ffma2(acc[2], pe1, wb.x);  ffma2(acc[3], pe1, wb.y);
        ffma2(acc[4], pe2, wa.x);  ffma2(acc[5], pe2, wa.y);
        ffma2(acc[6], pe2, wb.x);  ffma2(acc[7], pe2, wb.y);
        ffma2(acc[8], pe3, wa.x);  ffma2(acc[9], pe3, wa.y);
        ffma2(acc[10], pe3, wb.x); ffma2(acc[11], pe3, wb.y);
        ffma2(acc[12], pe4, wa.x); ffma2(acc[13], pe4, wa.y);
        ffma2(acc[14], pe4, wb.x); ffma2(acc[15], pe4, wb.y);
    }
}

template <int PLANE>
__device__ __forceinline__ void conv_store(const unsigned long long (&acc)[16],
                                           float* __restrict__ op,
                                           const float* __restrict__ bias,
                                           const float* __restrict__ bns,
                                           const float* __restrict__ bsh, int ocbase) {
#pragma unroll
    for (int j = 0; j < 4; j++) {
        int oc0 = ocbase + 2 * j;
        float bi0 = bias[oc0], sc0 = bns[oc0], sh0 = bsh[oc0];
        float bi1 = bias[oc0 + 1], sc1 = bns[oc0 + 1], sh1 = bsh[oc0 + 1];
        float4 v0, v1;
        v0.x = fmaxf(lo32(acc[0 + j]) + bi0, 0.f) * sc0 + sh0;
        v0.y = fmaxf(lo32(acc[4 + j]) + bi0, 0.f) * sc0 + sh0;
        v0.z = fmaxf(lo32(acc[8 + j]) + bi0, 0.f) * sc0 + sh0;
        v0.w = fmaxf(lo32(acc[12 + j]) + bi0, 0.f) * sc0 + sh0;
        v1.x = fmaxf(hi32(acc[0 + j]) + bi1, 0.f) * sc1 + sh1;
        v1.y = fmaxf(hi32(acc[4 + j]) + bi1, 0.f) * sc1 + sh1;
        v1.z = fmaxf(hi32(acc[8 + j]) + bi1, 0.f) * sc1 + sh1;
        v1.w = fmaxf(hi32(acc[12 + j]) + bi1, 0.f) * sc1 + sh1;
        *reinterpret_cast<float4*>(op + (size_t)(2 * j) * PLANE) = v0;
        *reinterpret_cast<float4*>(op + (size_t)(2 * j + 1) * PLANE) = v1;
    }
}

// ---------------------------------------------------------------------------
// conv1: 3 -> 32 ch, 255x255 -> 127x127 (row stride 128).  16x16 tile, 256 thr.
// ---------------------------------------------------------------------------
__global__ void __launch_bounds__(256) conv1_kernel(const float* __restrict__ in,
                                                    const float* __restrict__ bias) {
    __shared__ __align__(16) float s_in[3 * 33 * 40];
    __shared__ __align__(16) float s_w[27 * 32];
    const int b = blockIdx.y;
    const int tx = blockIdx.x & 7, ty = blockIdx.x >> 3;
    const int ox0t = tx * 16, oy0 = ty * 16;
    const int ix0 = 2 * ox0t, iy0 = 2 * oy0;

    if (threadIdx.x < 216)
        reinterpret_cast<float4*>(s_w)[threadIdx.x] =
            reinterpret_cast<const float4*>(g_wt1)[threadIdx.x];

    // fill: hoisted indexing (5 slots/thread), clamped loads (no branches)
    const float* inb = in + (size_t)b * 3 * 65025;
    int goff[5], soff[5];
#pragma unroll
    for (int k = 0; k < 5; k++) {
        int s = threadIdx.x + k * 256;
        s = min(s, 1088);
        int yy = s / 33, xx = s - yy * 33;
        int gy = min(iy0 + yy, 254), gx = min(ix0 + xx, 254);
        goff[k] = gy * 255 + gx;
        soff[k] = yy * 40 + ((xx & 1) ? 20 + (xx >> 1) : (xx >> 1));
    }
#pragma unroll
    for (int ic = 0; ic < 3; ic++) {
        float v[5];
#pragma unroll
        for (int k = 0; k < 5; k++) v[k] = inb[ic * 65025 + goff[k]];
#pragma unroll
        for (int k = 0; k < 5; k++) s_in[ic * 1320 + soff[k]] = v[k];
    }
    __syncthreads();

    const int xg = threadIdx.x & 3;
    const int y = (threadIdx.x >> 2) & 15;
    const int g = threadIdx.x >> 6;
    unsigned long long acc[16];
#pragma unroll
    for (int i = 0; i < 16; i++) acc[i] = 0ULL;

    const float* pw0 = s_w + g * 8;
#pragma unroll
    for (int ic = 0; ic < 3; ic++) {
        const float* prb = s_in + ic * 1320 + (2 * y) * 40 + 4 * xg;
#pragma unroll
        for (int kh = 0; kh < 3; kh++) {
            const float* pr = prb + kh * 40;
            float4 ev = *reinterpret_cast<const float4*>(pr);
            float e4 = pr[4];
            float4 od = *reinterpret_cast<const float4*>(pr + 20);
            conv_row_taps(acc, ev, e4, od, pw0 + (ic * 9 + kh * 3) * 32);
        }
    }

    const int oy = oy0 + y;
    const int ox0 = ox0t + 4 * xg;
    if (oy < 127) {
        float* op = g_buf1 + ((size_t)b * 32 + g * 8) * (127 * 128) + (size_t)oy * 128 + ox0;
        conv_store<127 * 128>(acc, op, bias, g_bns, g_bsh, g * 8);
    }
}

// ---------------------------------------------------------------------------
// conv2..5: 32 -> 32 ch.  16x16 tile, 256 thr (xg4 x y16 x g4), 4-ic x 8
// phases with software-pipelined register prefetch of inputs + weights.
// ---------------------------------------------------------------------------
template <int L, int IH, int IWS, int OH, int OWS, int TX>
__global__ void __launch_bounds__(256) conv32_kernel(const float* __restrict__ bias) {
    constexpr int IN_SLOTS = 4 * 33 * 9;            // 1188 float4
    constexpr int W_SLOTS = 288;                    // 1152 floats / 4
    constexpr int TOT_SLOTS = IN_SLOTS + W_SLOTS;   // 1476
    constexpr int SW_FL = 4 * 1320;                 // s_w float offset (5280)
    constexpr unsigned SW_B = SW_FL * 4;            // byte offset
    constexpr int IN_STEP = 4 * IH * IWS;           // floats per phase (input)
    constexpr int W_STEP = 1152;                    // floats per phase (weights)

    __shared__ __align__(16) float smem[SW_FL + 1152 + 8]; // s_in | s_w | dummy
    float* const s_in = smem;
    float* const s_w = smem + SW_FL;
    char* const smb = reinterpret_cast<char*>(smem);

    const int b = blockIdx.y;
    const int tx = blockIdx.x % TX, ty = blockIdx.x / TX;
    const int ox0t = tx * 16, oy0 = ty * 16;
    const int ix0 = 2 * ox0t, iy0 = 2 * oy0;
    const float* in = (L == 0) ? g_buf1 : (L == 1) ? g_buf2 : (L == 2) ? g_buf3 : g_buf4;
    float* out = (L == 0) ? g_buf2 : (L == 1) ? g_buf3 : (L == 2) ? g_buf4 : g_buf5;
    const float* inb = in + (size_t)b * 32 * IH * IWS;
    const float* wt = g_wtl + L * 9216;

    // per-thread fill slots
    const float* gp[6];
    unsigned sm1[6], sm2[6];
#pragma unroll
    for (int k = 0; k < 6; k++) {
        int s = threadIdx.x + k * 256;
        if (s < IN_SLOTS) {
            int ic = s / 297, r = s - ic * 297;
            int yy = r / 9, xq = r - yy * 9;
            int gy = min(iy0 + yy, IH - 1);
            gp[k] = inb + ((size_t)ic * IH + gy) * IWS + ix0 + 4 * xq;
            unsigned so = (unsigned)(ic * 1320 + yy * 40 + 2 * xq) * 4u;
            sm1[k] = so;
            sm2[k] = so + 80;
        } else if (s < TOT_SLOTS) {
            int idx = s - IN_SLOTS;
            gp[k] = wt + idx * 4;
            unsigned so = SW_B + (unsigned)idx * 16u;
            sm1[k] = so;
            sm2[k] = so + 8;
        } else {
            gp[k] = wt;
            sm1[k] = SW_B + 1152 * 4;
            sm2[k] = sm1[k] + 8;
        }
    }

    const int xg = threadIdx.x & 3;
    const int y = (threadIdx.x >> 2) & 15;
    const int g = threadIdx.x >> 6;
    unsigned long long acc[16];
#pragma unroll
    for (int i = 0; i < 16; i++) acc[i] = 0ULL;

    float4 pre[6];
#pragma unroll
    for (int k = 0; k < 6; k++) pre[k] = *reinterpret_cast<const float4*>(gp[k]);

    for (int ph = 0; ph < 8; ph++) {
#pragma unroll
        for (int k = 0; k < 6; k++) {
            float4 v = pre[k];
            bool isw = sm1[k] >= SW_B;
            float a1 = isw ? v.y : v.z; // 2nd elem of 1st pair
            float a2 = isw ? v.z : v.y; // 1st elem of 2nd pair
            *reinterpret_cast<float2*>(smb + sm1[k]) = make_float2(v.x, a1);
            *reinterpret_cast<float2*>(smb + sm2[k]) = make_float2(a2, v.w);
        }
        __syncthreads();
        if (ph < 7) {
#pragma unroll
            for (int k = 0; k < 6; k++) {
                gp[k] += (sm1[k] >= SW_B) ? W_STEP : IN_STEP;
                pre[k] = *reinterpret_cast<const float4*>(gp[k]);
            }
        }
        const float* pw0 = s_w + g * 8;
#pragma unroll
        for (int ic = 0; ic < 4; ic++) {
            const float* prb = s_in + ic * 1320 + (2 * y) * 40 + 4 * xg;
            const float* pw1 = pw0 + ic * 288;
#pragma unroll
            for (int kh = 0; kh < 3; kh++) {
                const float* pr = prb + kh * 40;
                float4 ev = *reinterpret_cast<const float4*>(pr);
                float e4 = pr[4];
                float4 od = *reinterpret_cast<const float4*>(pr + 20);
                conv_row_taps(acc, ev, e4, od, pw1 + kh * 96);
            }
        }
        if (ph < 7) __syncthreads();
    }

    const int oy = oy0 + y;
    const int ox0 = ox0t + 4 * xg;
    if (oy < OH && ox0 < OWS) {
        const float* bns = g_bns + (L + 1) * 32;
        const float* bsh = g_bsh + (L + 1) * 32;
        float* op = out + ((size_t)b * 32 + g * 8) * (OH * OWS) + (size_t)oy * OWS + ox0;
        conv_store<OH * OWS>(acc, op, bias, bns, bsh, g * 8);
    }
}

// ---------------------------------------------------------------------------
// FC(1568->20 relu) -> FC(20->10) -> Thomas tridiagonal solve (fp64) -> a,b,c.
// ---------------------------------------------------------------------------
__global__ void __launch_bounds__(256) fc_kernel(const float* __restrict__ l1w,
                                                 const float* __restrict__ l1b,
                                                 const float* __restrict__ l2w,
                                                 const float* __restrict__ l2b) {
    __shared__ float s_y[1568];
    __shared__ float s_h1[20];
    __shared__ float s_ys[10];
    const int b = blockIdx.x;
    const float* yb = g_buf5 + (size_t)b * 32 * 7 * 8;
    for (int i = threadIdx.x; i < 1568; i += 256) {
        int oc = i / 49, r = i % 49;
        s_y[i] = yb[oc * 56 + (r / 7) * 8 + (r % 7)];
    }
    __syncthreads();

    const int warp = threadIdx.x >> 5, lane = threadIdx.x & 31;
    for (int j = warp; j < 20; j += 8) {
        float s = 0.f;
        const float* w = l1w + (size_t)j * 1568;
        for (int k = lane; k < 1568; k += 32) s += s_y[k] * w[k];
#pragma unroll
        for (int o = 16; o > 0; o >>= 1) s += __shfl_down_sync(0xffffffffu, s, o);
        if (lane == 0) s_h1[j] = fmaxf(s + l1b[j], 0.f);
    }
    __syncthreads();

    if (threadIdx.x < 10) {
        float s = l2b[threadIdx.x];
        const float* w = l2w + threadIdx.x * 20;
#pragma unroll
        for (int j = 0; j < 20; j++) s += s_h1[j] * w[j];
        s_ys[threadIdx.x] = s;
    }
    __syncthreads();

    if (threadIdx.x == 0) {
        const double h = 1.0 / 9.0;
        double ys[10];
#pragma unroll
        for (int i = 0; i < 10; i++) ys[i] = (double)s_ys[i];
        double d[8], cp[8];
        for (int i = 0; i < 8; i++)
            d[i] = (6.0 / (h * h)) * (ys[i + 2] - 2.0 * ys[i + 1] + ys[i]);
        cp[0] = 0.25;
        d[0] *= 0.25;
        for (int i = 1; i < 8; i++) {
            double m = 4.0 - cp[i - 1];
            cp[i] = 1.0 / m;
            d[i] = (d[i] - d[i - 1]) / m;
        }
        double M[10];
        M[0] = 0.0;
        M[9] = 0.0;
        M[8] = d[7];
        for (int i = 6; i >= 0; i--) M[i + 1] = d[i] - cp[i] * M[i + 2];
        float* cf = g_coef + b * 27;
        for (int i = 0; i < 9; i++) {
            cf[i] = (float)((M[i + 1] - M[i]) / (6.0 * h));
            cf[9 + i] = (float)(M[i] * 0.5);
            cf[18 + i] = (float)((ys[i + 1] - ys[i]) / h - (M[i + 1] + 2.0 * M[i]) * (h / 6.0));
        }
    }
}

// ---------------------------------------------------------------------------
// eval: bucket via x*9 (exact __fdiv_rn only within 1e-4 of a knot; true
// discrepancy <= 2e-7 so the decision is always identical to x / h_f).
// float4 main loop with per-batch alignment peel.
// ---------------------------------------------------------------------------
__device__ __forceinline__ float evalpix(float x, const float* __restrict__ sc) {
    const float h = 1.0f / 9.0f;
    float tf = fminf(fmaxf(x * 9.0f, 0.f), 8.f);
    int xi = (int)tf;
    float fr = tf - (float)xi;
    if (fr < 1e-4f || fr > 0.9999f) {
        float te = fminf(fmaxf(__fdiv_rn(x, h), 0.f), 8.f);
        xi = (int)te;
    }
    float xf = x - (float)xi * h;
    return ((sc[xi] * xf + sc[9 + xi]) * xf + sc[18 + xi]) * xf;
}

__global__ void __launch_bounds__(256) eval_kernel(const float* __restrict__ in,
                                                   float* __restrict__ out) {
    __shared__ float s_c[27];
    const int b = blockIdx.y;
    if (threadIdx.x < 27) s_c[threadIdx.x] = g_coef[b * 27 + threadIdx.x];
    __syncthreads();
    const int N = 3 * 255 * 255; // 195075 (== 3 mod 4)
    const float* ib = in + (size_t)b * N;
    float* ob = out + (size_t)b * N;
    const int mis = (4 - ((3 * b) & 3)) & 3;
    const int nv = (N - mis) >> 2;
    const float4* iv = reinterpret_cast<const float4*>(ib + mis);
    float4* ov = reinterpret_cast<float4*>(ob + mis);
    for (int v = blockIdx.x * 256 + threadIdx.x; v < nv; v += gridDim.x * 256) {
        float4 x = iv[v];
        float4 r;
        r.x = evalpix(x.x, s_c);
        r.y = evalpix(x.y, s_c);
        r.z = evalpix(x.z, s_c);
        r.w = evalpix(x.w, s_c);
        ov[v] = r;
    }
    const int tail = N - mis - 4 * nv;
    if (blockIdx.x == 0 && threadIdx.x < mis + tail) {
        int t = threadIdx.x;
        int i = (t < mis) ? t : (mis + 4 * nv + (t - mis));
        ob[i] = evalpix(ib[i], s_c);
    }
}

// ---------------------------------------------------------------------------
extern "C" void kernel_launch(void* const* d_in, const int* in_sizes, int n_in,
                              void* d_out, int out_size) {
    const float* batch = (const float*)d_in[0];
    const float* c1w = (const float*)d_in[1];
    const float* c1b = (const float*)d_in[2];
    const float* cw = (const float*)d_in[3];
    const float* cb = (const float*)d_in[4];
    const float* bng = (const float*)d_in[5];
    const float* bnb = (const float*)d_in[6];
    const float* bnm = (const float*)d_in[7];
    const float* bnv = (const float*)d_in[8];
    const float* l1w = (const float*)d_in[9];
    const float* l1b = (const float*)d_in[10];
    const float* l2w = (const float*)d_in[11];
    const float* l2b = (const float*)d_in[12];
    float* out = (float*)d_out;

    prep_kernel<<<64, 256>>>(c1w, cw, bng, bnb, bnm, bnv);
    conv1_kernel<<<dim3(64, 64), 256>>>(batch, c1b);
    conv32_kernel<0, 127, 128, 63, 64, 4><<<dim3(16, 64), 256>>>(cb + 0);
    conv32_kernel<1, 63, 64, 31, 32, 2><<<dim3(4, 64), 256>>>(cb + 32);
    conv32_kernel<2, 31, 32, 15, 16, 1><<<dim3(1, 64), 256>>>(cb + 64);
    conv32_kernel<3, 15, 16, 7, 8, 1><<<dim3(1, 64), 256>>>(cb + 96);
    fc_kernel<<<64, 256>>>(l1w, l1b, l2w, l2b);
    eval_kernel<<<dim3(191, 64), 256>>>(batch, out);
}